// round 3
// baseline (speedup 1.0000x reference)
#include <cuda_runtime.h>

#define NB 4
#define NA 160000
#define NG 64

// Scratch: per-(batch, gt) highest IoU over all anchors, stored as float bits
// (IoU >= 0, so unsigned-int compare order == float compare order).
__device__ unsigned int g_highest_bits[NB * NG];

// IoU must be BIT-IDENTICAL between the two passes (the reference does
// mq == highest_per_gt). Use _rn intrinsics to forbid FMA contraction and the
// same fast divide in both kernels.
__device__ __forceinline__ float box_area(float4 b) {
    return __fmul_rn(__fadd_rn(b.z, -b.x), __fadd_rn(b.w, -b.y));
}

__device__ __forceinline__ float iou_pair(float4 a, float areaA, float4 g, float areaG) {
    float ltx = fmaxf(g.x, a.x);
    float lty = fmaxf(g.y, a.y);
    float rbx = fminf(g.z, a.z);
    float rby = fminf(g.w, a.w);
    float w = fmaxf(__fadd_rn(rbx, -ltx), 0.0f);
    float h = fmaxf(__fadd_rn(rby, -lty), 0.0f);
    float inter = __fmul_rn(w, h);
    float denom = __fadd_rn(__fadd_rn(areaA, areaG), -inter);
    return __fdividef(inter, denom);   // inter==0 -> exactly 0
}

__global__ void k_zero_highest() {
    g_highest_bits[threadIdx.x] = 0u;
}

// Pass 1: per-GT max IoU over all anchors.
// Each thread keeps 64 running maxes in registers; anchors read exactly once.
__global__ __launch_bounds__(256, 2)
void k_pergt_max(const float4* __restrict__ anchors, const float4* __restrict__ gts) {
    const int b = blockIdx.y;
    const int tid = threadIdx.x;

    __shared__ float4 sg[NG];
    __shared__ float sga[NG];
    __shared__ unsigned int smax[NG];

    if (tid < NG) {
        float4 g = gts[b * NG + tid];
        sg[tid] = g;
        sga[tid] = box_area(g);
        smax[tid] = 0u;
    }
    __syncthreads();

    float gmax[NG];
#pragma unroll
    for (int g = 0; g < NG; ++g) gmax[g] = 0.0f;

    const int stride = gridDim.x * blockDim.x;
    for (int a = blockIdx.x * blockDim.x + tid; a < NA; a += stride) {
        float4 an = anchors[b * NA + a];
        float areaA = box_area(an);
#pragma unroll
        for (int g = 0; g < NG; ++g) {
            float v = iou_pair(an, areaA, sg[g], sga[g]);
            gmax[g] = fmaxf(gmax[g], v);
        }
    }

    // Warp reduce each of the 64 maxes, then shared atomics, then global.
#pragma unroll
    for (int g = 0; g < NG; ++g) {
        float v = gmax[g];
#pragma unroll
        for (int off = 16; off; off >>= 1)
            v = fmaxf(v, __shfl_xor_sync(0xffffffffu, v, off));
        if ((tid & 31) == 0)
            atomicMax(&smax[g], __float_as_uint(v));
    }
    __syncthreads();
    if (tid < NG)
        atomicMax(&g_highest_bits[b * NG + tid], smax[tid]);
}

// Pass 2: one thread per anchor. Recompute IoUs (bit-identical), do the
// torchvision Matcher + softer-label logic, write labels + matched gt box.
__global__ __launch_bounds__(256)
void k_label(const float4* __restrict__ anchors, const float4* __restrict__ gts,
             const float* __restrict__ scores, const int* __restrict__ confs,
             float* __restrict__ outL, float4* __restrict__ outB) {
    const int b = blockIdx.y;
    const int tid = threadIdx.x;

    __shared__ float4 sg[NG];
    __shared__ float sga[NG];
    __shared__ float ss[NG];
    __shared__ float shigh[NG];
    __shared__ int sc[NG];

    if (tid < NG) {
        float4 g = gts[b * NG + tid];
        sg[tid] = g;
        sga[tid] = box_area(g);
        ss[tid] = scores[b * NG + tid];
        sc[tid] = confs[b * NG + tid];
        shigh[tid] = __uint_as_float(g_highest_bits[b * NG + tid]);
    }
    __syncthreads();

    const int a = blockIdx.x * 256 + tid;   // NA = 625*256 exactly
    float4 an = anchors[b * NA + a];
    float areaA = box_area(an);

    float best = -1.0f;    // all-zero column -> bestg stays 0 (first occurrence)
    int bestg = 0;
    bool lowq = false;
#pragma unroll
    for (int g = 0; g < NG; ++g) {
        float v = iou_pair(an, areaA, sg[g], sga[g]);
        lowq |= (v == shigh[g]);
        if (v > best) { best = v; bestg = g; }   // strict > = first-occurrence argmax
    }

    // Matcher: < 0.3 -> -1 ; < 0.7 -> -2 ; else matches. Low-quality override.
    int midx = lowq ? bestg
                    : (best >= 0.7f ? bestg : (best >= 0.3f ? -2 : -1));
    int cl = midx >= 0 ? midx : 0;

    float s = ss[cl];
    int c = sc[cl];
    // positive path: min(1, s) then forced -1 if s<1 or conf==0  => (s<1||c==0)?-1:1
    float label = (midx == -1) ? 0.0f
                : (midx == -2) ? -1.0f
                : ((s < 1.0f || c == 0) ? -1.0f : 1.0f);

    const int idx = b * NA + a;
    outL[idx] = label;
    outB[idx] = sg[cl];
}

extern "C" void kernel_launch(void* const* d_in, const int* in_sizes, int n_in,
                              void* d_out, int out_size) {
    (void)in_sizes; (void)n_in; (void)out_size;
    const float4* anchors = (const float4*)d_in[0];   // [B, A, 4] f32
    const float4* gts     = (const float4*)d_in[1];   // [B, G, 4] f32
    const float*  scores  = (const float*)d_in[2];    // [B, G] f32
    const int*    confs   = (const int*)d_in[3];      // [B, G] i32

    float*  outL = (float*)d_out;                     // labels [B, A]
    float4* outB = (float4*)((float*)d_out + NB * NA);// matched boxes [B, A, 4]

    k_zero_highest<<<1, NB * NG>>>();
    k_pergt_max<<<dim3(160, NB), 256>>>(anchors, gts);
    k_label<<<dim3(NA / 256, NB), 256>>>(anchors, gts, scores, confs, outL, outB);
}

// round 5
// speedup vs baseline: 3.5244x; 3.5244x over previous
#include <cuda_runtime.h>

#define NB 4
#define NA 160000
#define NG 64
#define NBLK 160            // K1 blocks per batch image
#define K1_STRIDE (NBLK*256) // 40960
#define NBLK4 145           // blocks 0..144 handle 4 anchors/thread, 145..159 handle 3

// Scratch (__device__ globals; no init required by construction)
__device__ uint2        g_best[NB * NA];            // (float bits of best IoU, argmax gt)
__device__ float        g_blockmax[NB * NBLK * NG]; // per-block per-gt column max
__device__ unsigned char g_lowq[NB * NA];           // low-quality flags (zeroed by K1)

// IoU must be BIT-IDENTICAL everywhere it is computed (K1 colmax vs K2 rescan
// equality). _rn intrinsics forbid FMA contraction; __fdividef used uniformly.
__device__ __forceinline__ float box_area(float4 b) {
    return __fmul_rn(__fadd_rn(b.z, -b.x), __fadd_rn(b.w, -b.y));
}

__device__ __forceinline__ float iou_pair(float4 a, float areaA, float4 g, float areaG) {
    float ltx = fmaxf(g.x, a.x);
    float lty = fmaxf(g.y, a.y);
    float rbx = fminf(g.z, a.z);
    float rby = fminf(g.w, a.w);
    float w = fmaxf(__fadd_rn(rbx, -ltx), 0.0f);
    float h = fmaxf(__fadd_rn(rby, -lty), 0.0f);
    float inter = __fmul_rn(w, h);
    float denom = __fadd_rn(__fadd_rn(areaA, areaG), -inter);
    return __fdividef(inter, denom);   // inter==0 -> exactly 0
}

// ---------------------------------------------------------------------------
// K1: the ONLY full IoU pass. Per thread: KA anchors held in registers.
// Produces: per-anchor (best, bestg); per-block per-gt column max; zeroed lowq.
// ---------------------------------------------------------------------------
template <int KA>
__device__ __forceinline__ void k1_body(
    const float4* __restrict__ anchors, int b, int blk, int tid,
    const float4* sg, const float* sga, unsigned int* smax)
{
    const int a0 = blk * 256 + tid;

    float4 an[KA]; float areaA[KA]; float best[KA]; int bestg[KA];
#pragma unroll
    for (int k = 0; k < KA; ++k) {
        int a = a0 + k * K1_STRIDE;
        an[k] = anchors[b * NA + a];
        areaA[k] = box_area(an[k]);
        best[k] = -1.0f;
        bestg[k] = 0;
        g_lowq[b * NA + a] = 0;   // each anchor touched exactly once -> free zeroing
    }

    float gmax[NG];
#pragma unroll
    for (int g = 0; g < NG; ++g) gmax[g] = 0.0f;

#pragma unroll
    for (int g = 0; g < NG; ++g) {
        float4 gb = sg[g];
        float  ag = sga[g];
#pragma unroll
        for (int k = 0; k < KA; ++k) {
            float v = iou_pair(an[k], areaA[k], gb, ag);
            gmax[g] = fmaxf(gmax[g], v);
            if (v > best[k]) { best[k] = v; bestg[k] = g; }  // strict > : first occurrence
        }
    }

#pragma unroll
    for (int k = 0; k < KA; ++k) {
        int a = a0 + k * K1_STRIDE;
        g_best[b * NA + a] = make_uint2(__float_as_uint(best[k]), (unsigned)bestg[k]);
    }

    // Column-max reduce: warp shuffles then shared atomics (IoU>=0 so uint order ok)
#pragma unroll
    for (int g = 0; g < NG; ++g) {
        float v = gmax[g];
#pragma unroll
        for (int off = 16; off; off >>= 1)
            v = fmaxf(v, __shfl_xor_sync(0xffffffffu, v, off));
        if ((tid & 31) == 0)
            atomicMax(&smax[g], __float_as_uint(v));
    }
}

__global__ __launch_bounds__(256, 1)
void k_main(const float4* __restrict__ anchors, const float4* __restrict__ gts)
{
    const int b = blockIdx.y;
    const int blk = blockIdx.x;
    const int tid = threadIdx.x;

    __shared__ float4 sg[NG];
    __shared__ float  sga[NG];
    __shared__ unsigned int smax[NG];

    if (tid < NG) {
        float4 g = gts[b * NG + tid];
        sg[tid] = g;
        sga[tid] = box_area(g);
        smax[tid] = 0u;
    }
    __syncthreads();

    if (blk < NBLK4) k1_body<4>(anchors, b, blk, tid, sg, sga, smax);
    else             k1_body<3>(anchors, b, blk, tid, sg, sga, smax);

    __syncthreads();
    if (tid < NG)
        g_blockmax[(b * NBLK + blk) * NG + tid] = __uint_as_float(smax[tid]);
}

// ---------------------------------------------------------------------------
// K2: sparse low-quality pass. One block per (gt, batch) column: find global
// column max from 160 block maxima, rescan only blocks achieving it.
// ---------------------------------------------------------------------------
__global__ __launch_bounds__(256)
void k_lowq(const float4* __restrict__ anchors, const float4* __restrict__ gts)
{
    const int g = blockIdx.x;
    const int b = blockIdx.y;
    const int tid = threadIdx.x;

    __shared__ float red[256];
    __shared__ int   list[NBLK];
    __shared__ int   cnt;

    if (tid == 0) cnt = 0;
    float m = (tid < NBLK) ? g_blockmax[(b * NBLK + tid) * NG + g] : 0.0f;
    red[tid] = m;
    __syncthreads();
#pragma unroll
    for (int s = 128; s; s >>= 1) {
        if (tid < s) red[tid] = fmaxf(red[tid], red[tid + s]);
        __syncthreads();
    }
    const float shigh = red[0];

    if (tid < NBLK && m == shigh) {      // winner block(s) match bit-exactly
        int i = atomicAdd(&cnt, 1);
        list[i] = tid;
    }
    __syncthreads();

    const int n = cnt;
    float4 gb = gts[b * NG + g];
    float  ag = box_area(gb);            // identical formula -> identical bits

    for (int i = 0; i < n; ++i) {
        int blk = list[i];
#pragma unroll
        for (int k = 0; k < 4; ++k) {
            int a = blk * 256 + k * K1_STRIDE + tid;
            if (a < NA) {
                float4 an = anchors[b * NA + a];
                float v = iou_pair(an, box_area(an), gb, ag);
                if (v == shigh) g_lowq[b * NA + a] = 1;
            }
        }
    }
}

// ---------------------------------------------------------------------------
// K3: label + matched-box writer. Pure memory + a handful of selects.
// ---------------------------------------------------------------------------
__global__ __launch_bounds__(256)
void k_label(const float4* __restrict__ gts, const float* __restrict__ scores,
             const int* __restrict__ confs,
             float* __restrict__ outL, float4* __restrict__ outB)
{
    const int b = blockIdx.y;
    const int tid = threadIdx.x;

    __shared__ float4 sg[NG];
    __shared__ float  ss[NG];
    __shared__ int    sc[NG];
    if (tid < NG) {
        sg[tid] = gts[b * NG + tid];
        ss[tid] = scores[b * NG + tid];
        sc[tid] = confs[b * NG + tid];
    }
    __syncthreads();

    const int a = blockIdx.x * 256 + tid;   // NA = 625*256 exactly
    const int idx = b * NA + a;

    uint2 bb = g_best[idx];
    float best = __uint_as_float(bb.x);
    int bestg = (int)bb.y;
    bool lowq = g_lowq[idx] != 0;

    // Matcher: <0.3 -> -1 ; <0.7 -> -2 ; else match. Low-quality override.
    int midx = lowq ? bestg
                    : (best >= 0.7f ? bestg : (best >= 0.3f ? -2 : -1));
    int cl = midx >= 0 ? midx : 0;

    float s = ss[cl];
    int c = sc[cl];
    float label = (midx == -1) ? 0.0f
                : (midx == -2) ? -1.0f
                : ((s < 1.0f || c == 0) ? -1.0f : 1.0f);

    outL[idx] = label;
    outB[idx] = sg[cl];
}

extern "C" void kernel_launch(void* const* d_in, const int* in_sizes, int n_in,
                              void* d_out, int out_size) {
    (void)in_sizes; (void)n_in; (void)out_size;
    const float4* anchors = (const float4*)d_in[0];   // [B, A, 4] f32
    const float4* gts     = (const float4*)d_in[1];   // [B, G, 4] f32
    const float*  scores  = (const float*)d_in[2];    // [B, G] f32
    const int*    confs   = (const int*)d_in[3];      // [B, G] i32

    float*  outL = (float*)d_out;                      // labels [B, A]
    float4* outB = (float4*)((float*)d_out + NB * NA); // matched boxes [B, A, 4]

    k_main <<<dim3(NBLK, NB), 256>>>(anchors, gts);
    k_lowq <<<dim3(NG,   NB), 256>>>(anchors, gts);
    k_label<<<dim3(NA / 256, NB), 256>>>(gts, scores, confs, outL, outB);
}